// round 3
// baseline (speedup 1.0000x reference)
#include <cuda_runtime.h>
#include <cuda_bf16.h>

#define NX 128
#define NYY 128
#define NTT 64
#define BQ 2048
#define KT 128
#define DM 64
#define NH 4
#define HDIM 16
#define NLAY 2
#define DFFN 128

#define HR 68              // padded row stride for 64-wide rows (conflict-free float4)
#define FR 132             // padded row stride for 128-wide ff rows
#define SM_H 0
#define SM_Q 8704
#define SM_K 17408
#define SM_V 26112
#define SM_W 34816
#define SM_TOT 55296       // floats -> 221184 bytes

extern __shared__ __align__(16) float smem[];

__device__ __forceinline__ void ln_row(float* hrow, const float* sp, const float* bp) {
    float4 xr[16];
#pragma unroll
    for (int c = 0; c < 16; c++) xr[c] = ((const float4*)hrow)[c];
    float m = 0.f;
#pragma unroll
    for (int c = 0; c < 16; c++) m += (xr[c].x + xr[c].y) + (xr[c].z + xr[c].w);
    m *= (1.f / 64.f);
    float v = 0.f;
#pragma unroll
    for (int c = 0; c < 16; c++) {
        float d0 = xr[c].x - m, d1 = xr[c].y - m, d2 = xr[c].z - m, d3 = xr[c].w - m;
        v += (d0 * d0 + d1 * d1) + (d2 * d2 + d3 * d3);
    }
    v *= (1.f / 64.f);
    float rs = rsqrtf(v + 1e-5f);
#pragma unroll
    for (int c = 0; c < 16; c++) {
        float4 x = xr[c];
        float4 s4 = ((const float4*)sp)[c];
        float4 b4 = ((const float4*)bp)[c];
        ((float4*)hrow)[c] = make_float4((x.x - m) * rs * s4.x + b4.x,
                                         (x.y - m) * rs * s4.y + b4.y,
                                         (x.z - m) * rs * s4.z + b4.z,
                                         (x.w - m) * rs * s4.w + b4.w);
    }
}

__global__ void __launch_bounds__(128, 1) ffkernel(
    const int* __restrict__ q_lin_idx,
    const int* __restrict__ offsets,
    const float* __restrict__ coords,
    const float* __restrict__ vals,
    const float* __restrict__ log_gammas,
    const float* __restrict__ w_in,
    const float* __restrict__ b_in,
    const float* __restrict__ qkv_w,
    const float* __restrict__ qkv_b,
    const float* __restrict__ out_w,
    const float* __restrict__ out_b,
    const float* __restrict__ ln1_s,
    const float* __restrict__ ln1_b,
    const float* __restrict__ ff1_w,
    const float* __restrict__ ff1_b,
    const float* __restrict__ ff2_w,
    const float* __restrict__ ff2_b,
    const float* __restrict__ ln2_s,
    const float* __restrict__ ln2_b,
    const float* __restrict__ head_ln_s,
    const float* __restrict__ head_ln_b,
    const float* __restrict__ head_w1,
    const float* __restrict__ head_b1,
    const float* __restrict__ head_w2,
    const float* __restrict__ head_b2,
    float* __restrict__ out)
{
    const int t = threadIdx.x;
    const int b = blockIdx.x;

    float* sh_h = smem + SM_H;
    float* sh_q = smem + SM_Q;
    float* sh_k = smem + SM_K;
    float* sh_v = smem + SM_V;
    float* sh_w = smem + SM_W;
    float* hrow = sh_h + t * HR;

    // ---------------- token build ----------------
    {
        int qi = q_lin_idx[b];
        int ii = qi / (NYY * NTT);
        int rr = qi % (NYY * NTT);
        int jj = rr / NTT;
        int kk0 = rr % NTT;
        int di = offsets[t * 3 + 0], dj = offsets[t * 3 + 1], dk = offsets[t * 3 + 2];
        int I = (ii + di) & (NX - 1);
        int J = (jj + dj) & (NYY - 1);
        int Kc = (kk0 + dk) & (NTT - 1);
        int nb = I * (NYY * NTT) + J * NTT + Kc;
        float qx = coords[qi * 3 + 0], qy = coords[qi * 3 + 1], qz = coords[qi * 3 + 2];
        float nx = coords[nb * 3 + 0], ny = coords[nb * 3 + 1], nz = coords[nb * 3 + 2];
        float g0 = __expf(log_gammas[0]);
        float g1 = __expf(log_gammas[1]);
        float g2 = __expf(log_gammas[2]);
        float ux = nx - qx + 0.5f; ux -= floorf(ux); ux -= 0.5f;
        float uy = ny - qy + 0.5f; uy -= floorf(uy); uy -= 0.5f;
        float uz = nz - qz + 0.5f; uz -= floorf(uz); uz -= 0.5f;
        float t0 = ux * g0, t1 = uy * g1, t2 = uz * g2, t3 = vals[nb];
#pragma unroll 4
        for (int d = 0; d < DM; d++) {
            float a = b_in[d] + t0 * w_in[d * 4 + 0] + t1 * w_in[d * 4 + 1]
                              + t2 * w_in[d * 4 + 2] + t3 * w_in[d * 4 + 3];
            hrow[d] = a;
        }
    }

    // ---------------- layers ----------------
    for (int l = 0; l < NLAY; l++) {
        // stage qkv weights (12288 floats) into sh_w
        {
            const float4* src = (const float4*)(qkv_w + l * 3 * DM * DM);
            float4* dst = (float4*)sh_w;
            for (int idx = t; idx < (3 * DM * DM) / 4; idx += 128) dst[idx] = src[idx];
        }
        __syncthreads();

        // ---- QKV projection (row-local) ----
        {
            float4 hreg[16];
#pragma unroll
            for (int c = 0; c < 16; c++) hreg[c] = ((const float4*)hrow)[c];
            const float* qb = qkv_b + l * 3 * DM;
            for (int j4 = 0; j4 < 3 * DM; j4 += 4) {
                float a0 = qb[j4 + 0], a1 = qb[j4 + 1], a2 = qb[j4 + 2], a3 = qb[j4 + 3];
                const float4* w0p = (const float4*)(sh_w + (j4 + 0) * DM);
                const float4* w1p = (const float4*)(sh_w + (j4 + 1) * DM);
                const float4* w2p = (const float4*)(sh_w + (j4 + 2) * DM);
                const float4* w3p = (const float4*)(sh_w + (j4 + 3) * DM);
#pragma unroll
                for (int c = 0; c < 16; c++) {
                    float4 h4 = hreg[c];
                    float4 w0 = w0p[c], w1 = w1p[c], w2 = w2p[c], w3 = w3p[c];
                    a0 += h4.x * w0.x + h4.y * w0.y + h4.z * w0.z + h4.w * w0.w;
                    a1 += h4.x * w1.x + h4.y * w1.y + h4.z * w1.z + h4.w * w1.w;
                    a2 += h4.x * w2.x + h4.y * w2.y + h4.z * w2.z + h4.w * w2.w;
                    a3 += h4.x * w3.x + h4.y * w3.y + h4.z * w3.z + h4.w * w3.w;
                }
                float* dst;
                if (j4 < DM)            dst = sh_q + t * HR + j4;
                else if (j4 < 2 * DM)   dst = sh_k + t * HR + (j4 - DM);
                else                    dst = sh_v + t * HR + (j4 - 2 * DM);
                *(float4*)dst = make_float4(a0, a1, a2, a3);
            }
        }
        __syncthreads();

        // ---- attention (cross-token reads of k,v; q/o row-local) ----
        {
            const float ascale = 0.25f;  // 1/sqrt(HD=16)
#pragma unroll 1
            for (int hh = 0; hh < NH; hh++) {
                float* qrow = sh_q + t * HR + hh * HDIM;
                float4 q0 = ((const float4*)qrow)[0];
                float4 q1 = ((const float4*)qrow)[1];
                float4 q2 = ((const float4*)qrow)[2];
                float4 q3 = ((const float4*)qrow)[3];
                float4 o0 = make_float4(0, 0, 0, 0), o1 = o0, o2 = o0, o3 = o0;
                float lsum = 0.f;
#pragma unroll 2
                for (int kk = 0; kk < KT; kk++) {
                    const float4* krow = (const float4*)(sh_k + kk * HR + hh * HDIM);
                    float4 k0 = krow[0], k1 = krow[1], k2 = krow[2], k3 = krow[3];
                    float p0 = q0.x * k0.x + q0.y * k0.y + q0.z * k0.z + q0.w * k0.w;
                    float p1 = q1.x * k1.x + q1.y * k1.y + q1.z * k1.z + q1.w * k1.w;
                    float p2 = q2.x * k2.x + q2.y * k2.y + q2.z * k2.z + q2.w * k2.w;
                    float p3 = q3.x * k3.x + q3.y * k3.y + q3.z * k3.z + q3.w * k3.w;
                    float s = (p0 + p1) + (p2 + p3);
                    float p = __expf(s * ascale);
                    lsum += p;
                    const float4* vrow = (const float4*)(sh_v + kk * HR + hh * HDIM);
                    float4 v0 = vrow[0], v1 = vrow[1], v2 = vrow[2], v3 = vrow[3];
                    o0.x += p * v0.x; o0.y += p * v0.y; o0.z += p * v0.z; o0.w += p * v0.w;
                    o1.x += p * v1.x; o1.y += p * v1.y; o1.z += p * v1.z; o1.w += p * v1.w;
                    o2.x += p * v2.x; o2.y += p * v2.y; o2.z += p * v2.z; o2.w += p * v2.w;
                    o3.x += p * v3.x; o3.y += p * v3.y; o3.z += p * v3.z; o3.w += p * v3.w;
                }
                float inv = 1.0f / lsum;
                ((float4*)qrow)[0] = make_float4(o0.x * inv, o0.y * inv, o0.z * inv, o0.w * inv);
                ((float4*)qrow)[1] = make_float4(o1.x * inv, o1.y * inv, o1.z * inv, o1.w * inv);
                ((float4*)qrow)[2] = make_float4(o2.x * inv, o2.y * inv, o2.z * inv, o2.w * inv);
                ((float4*)qrow)[3] = make_float4(o3.x * inv, o3.y * inv, o3.z * inv, o3.w * inv);
            }
        }
        __syncthreads();   // attention done reading k,v; safe to re-stage sh_w and reuse k/v as ff scratch

        // stage out_w (4096) + ff1_w (8192) + ff2_w (8192) into sh_w
        {
            const float4* s0 = (const float4*)(out_w + l * DM * DM);
            const float4* s1 = (const float4*)(ff1_w + l * DFFN * DM);
            const float4* s2 = (const float4*)(ff2_w + l * DM * DFFN);
            float4* d0 = (float4*)(sh_w);
            float4* d1 = (float4*)(sh_w + 4096);
            float4* d2 = (float4*)(sh_w + 12288);
            for (int idx = t; idx < 1024; idx += 128) d0[idx] = s0[idx];
            for (int idx = t; idx < 2048; idx += 128) d1[idx] = s1[idx];
            for (int idx = t; idx < 2048; idx += 128) d2[idx] = s2[idx];
        }
        __syncthreads();

        // ---- out projection + residual + LN1 (row-local) ----
        {
            float4 og[16];
#pragma unroll
            for (int c = 0; c < 16; c++) og[c] = ((const float4*)(sh_q + t * HR))[c];
            const float* ob = out_b + l * DM;
            for (int j4 = 0; j4 < DM; j4 += 4) {
                float a0 = ob[j4 + 0], a1 = ob[j4 + 1], a2 = ob[j4 + 2], a3 = ob[j4 + 3];
                const float4* w0p = (const float4*)(sh_w + (j4 + 0) * DM);
                const float4* w1p = (const float4*)(sh_w + (j4 + 1) * DM);
                const float4* w2p = (const float4*)(sh_w + (j4 + 2) * DM);
                const float4* w3p = (const float4*)(sh_w + (j4 + 3) * DM);
#pragma unroll
                for (int c = 0; c < 16; c++) {
                    float4 x = og[c];
                    float4 w0 = w0p[c], w1 = w1p[c], w2 = w2p[c], w3 = w3p[c];
                    a0 += x.x * w0.x + x.y * w0.y + x.z * w0.z + x.w * w0.w;
                    a1 += x.x * w1.x + x.y * w1.y + x.z * w1.z + x.w * w1.w;
                    a2 += x.x * w2.x + x.y * w2.y + x.z * w2.z + x.w * w2.w;
                    a3 += x.x * w3.x + x.y * w3.y + x.z * w3.z + x.w * w3.w;
                }
                float4 ho = *(const float4*)(hrow + j4);
                *(float4*)(hrow + j4) = make_float4(ho.x + a0, ho.y + a1, ho.z + a2, ho.w + a3);
            }
            ln_row(hrow, ln1_s + l * DM, ln1_b + l * DM);
        }

        // ---- FF1: h(64) -> relu -> ff(128), write to scratch (aliases k/v) ----
        {
            float4 hreg[16];
#pragma unroll
            for (int c = 0; c < 16; c++) hreg[c] = ((const float4*)hrow)[c];
            float* frow = smem + SM_K + t * FR;
            const float* f1b = ff1_b + l * DFFN;
            for (int j4 = 0; j4 < DFFN; j4 += 4) {
                float a0 = f1b[j4 + 0], a1 = f1b[j4 + 1], a2 = f1b[j4 + 2], a3 = f1b[j4 + 3];
                const float4* w0p = (const float4*)(sh_w + 4096 + (j4 + 0) * DM);
                const float4* w1p = (const float4*)(sh_w + 4096 + (j4 + 1) * DM);
                const float4* w2p = (const float4*)(sh_w + 4096 + (j4 + 2) * DM);
                const float4* w3p = (const float4*)(sh_w + 4096 + (j4 + 3) * DM);
#pragma unroll
                for (int c = 0; c < 16; c++) {
                    float4 x = hreg[c];
                    float4 w0 = w0p[c], w1 = w1p[c], w2 = w2p[c], w3 = w3p[c];
                    a0 += x.x * w0.x + x.y * w0.y + x.z * w0.z + x.w * w0.w;
                    a1 += x.x * w1.x + x.y * w1.y + x.z * w1.z + x.w * w1.w;
                    a2 += x.x * w2.x + x.y * w2.y + x.z * w2.z + x.w * w2.w;
                    a3 += x.x * w3.x + x.y * w3.y + x.z * w3.z + x.w * w3.w;
                }
                *(float4*)(frow + j4) = make_float4(fmaxf(a0, 0.f), fmaxf(a1, 0.f),
                                                    fmaxf(a2, 0.f), fmaxf(a3, 0.f));
            }

            // ---- FF2: ff(128) -> 64, + residual + LN2 (row-local) ----
            float4 ffr[32];
#pragma unroll
            for (int c = 0; c < 32; c++) ffr[c] = ((const float4*)frow)[c];
            const float* f2b = ff2_b + l * DM;
            for (int j4 = 0; j4 < DM; j4 += 4) {
                float a0 = f2b[j4 + 0], a1 = f2b[j4 + 1], a2 = f2b[j4 + 2], a3 = f2b[j4 + 3];
                const float4* w0p = (const float4*)(sh_w + 12288 + (j4 + 0) * DFFN);
                const float4* w1p = (const float4*)(sh_w + 12288 + (j4 + 1) * DFFN);
                const float4* w2p = (const float4*)(sh_w + 12288 + (j4 + 2) * DFFN);
                const float4* w3p = (const float4*)(sh_w + 12288 + (j4 + 3) * DFFN);
#pragma unroll
                for (int c = 0; c < 32; c++) {
                    float4 x = ffr[c];
                    float4 w0 = w0p[c], w1 = w1p[c], w2 = w2p[c], w3 = w3p[c];
                    a0 += x.x * w0.x + x.y * w0.y + x.z * w0.z + x.w * w0.w;
                    a1 += x.x * w1.x + x.y * w1.y + x.z * w1.z + x.w * w1.w;
                    a2 += x.x * w2.x + x.y * w2.y + x.z * w2.z + x.w * w2.w;
                    a3 += x.x * w3.x + x.y * w3.y + x.z * w3.z + x.w * w3.w;
                }
                float4 ho = *(const float4*)(hrow + j4);
                *(float4*)(hrow + j4) = make_float4(ho.x + a0, ho.y + a1, ho.z + a2, ho.w + a3);
            }
            ln_row(hrow, ln2_s + l * DM, ln2_b + l * DM);
        }
        __syncthreads();  // end of layer: protects sh_w restage & scratch reuse
    }

    // ---------------- head ----------------
    if (t < DM) {
        float s0 = 0.f, s1 = 0.f, s2 = 0.f, s3 = 0.f;
        for (int tt = 0; tt < KT; tt += 4) {
            s0 += sh_h[(tt + 0) * HR + t];
            s1 += sh_h[(tt + 1) * HR + t];
            s2 += sh_h[(tt + 2) * HR + t];
            s3 += sh_h[(tt + 3) * HR + t];
        }
        sh_w[t] = (s0 + s1 + s2 + s3) * (1.f / (float)KT);
    }
    __syncthreads();
    {
        float m = 0.f;
#pragma unroll 8
        for (int c = 0; c < DM; c++) m += sh_w[c];
        m *= (1.f / 64.f);
        float var = 0.f;
#pragma unroll 8
        for (int c = 0; c < DM; c++) { float d = sh_w[c] - m; var += d * d; }
        var *= (1.f / 64.f);
        float rs = rsqrtf(var + 1e-5f);
        __syncthreads();
        if (t < DM) sh_w[64 + t] = (sh_w[t] - m) * rs * head_ln_s[t] + head_ln_b[t];
    }
    __syncthreads();
    if (t < DM) {
        float a = head_b1[t];
#pragma unroll 8
        for (int c = 0; c < DM; c++) a += sh_w[64 + c] * head_w1[t * DM + c];
        float g = 0.5f * a * (1.f + erff(a * 0.70710678118654752f));
        sh_w[128 + t] = g * head_w2[t];
    }
    __syncthreads();
    if (t == 0) {
        float s = head_b2[0];
        for (int c = 0; c < DM; c++) s += sh_w[128 + c];
        out[b] = s;
    }
}

extern "C" void kernel_launch(void* const* d_in, const int* in_sizes, int n_in,
                              void* d_out, int out_size) {
    const int*   q_lin_idx = (const int*)d_in[0];
    const int*   offsets   = (const int*)d_in[1];
    const float* coords    = (const float*)d_in[2];
    const float* vals      = (const float*)d_in[3];
    const float* log_gam   = (const float*)d_in[4];
    const float* w_in      = (const float*)d_in[5];
    const float* b_in      = (const float*)d_in[6];
    const float* qkv_w     = (const float*)d_in[7];
    const float* qkv_b     = (const float*)d_in[8];
    const float* out_w     = (const float*)d_in[9];
    const float* out_b     = (const float*)d_in[10];
    const float* ln1_s     = (const float*)d_in[11];
    const float* ln1_b     = (const float*)d_in[12];
    const float* ff1_w     = (const float*)d_in[13];
    const float* ff1_b     = (const float*)d_in[14];
    const float* ff2_w     = (const float*)d_in[15];
    const float* ff2_b     = (const float*)d_in[16];
    const float* ln2_s     = (const float*)d_in[17];
    const float* ln2_b     = (const float*)d_in[18];
    const float* head_ln_s = (const float*)d_in[19];
    const float* head_ln_b = (const float*)d_in[20];
    const float* head_w1   = (const float*)d_in[21];
    const float* head_b1   = (const float*)d_in[22];
    const float* head_w2   = (const float*)d_in[23];
    const float* head_b2   = (const float*)d_in[24];

    size_t smem_bytes = (size_t)SM_TOT * sizeof(float);
    cudaFuncSetAttribute(ffkernel, cudaFuncAttributeMaxDynamicSharedMemorySize, (int)smem_bytes);

    ffkernel<<<BQ, 128, smem_bytes>>>(
        q_lin_idx, offsets, coords, vals, log_gam, w_in, b_in,
        qkv_w, qkv_b, out_w, out_b, ln1_s, ln1_b,
        ff1_w, ff1_b, ff2_w, ff2_b, ln2_s, ln2_b,
        head_ln_s, head_ln_b, head_w1, head_b1, head_w2, head_b2,
        (float*)d_out);
}